// round 2
// baseline (speedup 1.0000x reference)
#include <cuda_runtime.h>

// Outputs concatenated (row-major, fp32), 96 elements total:
//   [ 0,16) x3 = a@b.T   [16,32) x4 = x3.T   [32,40) v1 = a
//   [40,48) v2 = a.T     [48,52) v3 = a.T@a  [52,68) v4 = a@a.T
//   [68,72) v5 = b.T@a   [72,88) v6 = x3     [88,96) v7 = a.T
// a = x1.reshape(4,2), b = x2.reshape(4,2) (row-major flat).
//
// Canonical classes:
//   dot2: r = x1[ia*2]*q[ib*2] + x1[ia*2+1]*q[ib*2+1]   (x3,x4,v4,v6)
//   dot4: r = sum_k p[k*2+i]*x1[k*2+j]                  (v3,v5)
//   copy: r = x1[permuted idx]                           (v1,v2,v7)

__global__ void __launch_bounds__(96, 1)
model_kernel(const float* __restrict__ x1,
             const float* __restrict__ x2,
             float* __restrict__ out) {
    const int o = threadIdx.x;
    if (o >= 96) return;

    const bool is_dot2 = (o < 32) || (o >= 52 && o < 68) || (o >= 72 && o < 88);
    const bool is_dot4 = (o >= 48 && o < 52) || (o >= 68 && o < 72);

    float r;
    if (is_dot2) {
        // segment-local index
        const int t  = (o < 32) ? (o & 15) : ((o < 68) ? (o - 52) : (o - 72));
        const bool swap = (o >= 16 && o < 32);            // x4 = x3.T
        const int ia = swap ? (t & 3) : (t >> 2);
        const int ib = swap ? (t >> 2) : (t & 3);
        const float* q = (o >= 52 && o < 68) ? x1 : x2;   // v4 uses q = a
        r = x1[ia * 2] * q[ib * 2] + x1[ia * 2 + 1] * q[ib * 2 + 1];
    } else if (is_dot4) {
        const int t = (o < 52) ? (o - 48) : (o - 68);
        const float* p = (o < 52) ? x1 : x2;              // v3: a.T@a, v5: b.T@a
        const int i = t >> 1, j = t & 1;
        r = p[0 + i] * x1[0 + j] + p[2 + i] * x1[2 + j]
          + p[4 + i] * x1[4 + j] + p[6 + i] * x1[6 + j];
    } else {
        if (o < 40) {                                     // v1 == x1 flat
            r = x1[o - 32];
        } else {                                          // v2 / v7: a.T
            const int t = (o < 48) ? (o - 40) : (o - 88);
            r = x1[(t & 3) * 2 + (t >> 2)];
        }
    }
    out[o] = r;
}

extern "C" void kernel_launch(void* const* d_in, const int* in_sizes, int n_in,
                              void* d_out, int out_size) {
    const float* x1 = (const float*)d_in[0];
    const float* x2 = (const float*)d_in[1];
    float* out = (float*)d_out;
    model_kernel<<<1, 96>>>(x1, x2, out);
}

// round 3
// speedup vs baseline: 1.0066x; 1.0066x over previous
#include <cuda_runtime.h>

// 96 fp32 outputs, a = x1.reshape(4,2), b = x2.reshape(4,2):
//   [ 0,16) x3 = a@b.T   [16,32) x4 = x3.T   [32,40) v1 = a
//   [40,48) v2 = a.T     [48,52) v3 = a.T@a  [52,68) v4 = a@a.T
//   [68,72) v5 = b.T@a   [72,88) v6 = x3     [88,96) v7 = a.T
//
// Thread->output remap so each warp runs ONE canonical class:
//   warp 0 (t  0..31): x3, x4          (dot2, q=x2, swap for x4)
//   warp 1 (t 32..63): v4, v6          (dot2, q = x1 / x2 via select)
//   warp 2 (t 64..95): v1,v2,v7 copies + v3,v5 dot4 (one branch)

__global__ void __launch_bounds__(96, 1)
model_kernel(const float* __restrict__ x1,
             const float* __restrict__ x2,
             float* __restrict__ out) {
    const int t = threadIdx.x;
    if (t >= 96) return;

    if (t < 64) {
        // ---- dot2 warps: r = x1[ia*2]*q[ib*2] + x1[ia*2+1]*q[ib*2+1]
        const int u = t & 31;
        const int v = u & 15;
        int ia, ib, pos;
        const float* q;
        if (t < 32) {                       // warp 0: x3 (u<16), x4 (u>=16)
            const bool swap = u >= 16;      // x4[i][j] = x3[j][i]
            ia = swap ? (v & 3) : (v >> 2);
            ib = swap ? (v >> 2) : (v & 3);
            q = x2;
            pos = t;                        // out 0..31
        } else {                            // warp 1: v4 (u<16), v6 (u>=16)
            ia = v >> 2;
            ib = v & 3;
            const bool is_v4 = u < 16;
            q = is_v4 ? x1 : x2;
            pos = is_v4 ? (52 + v) : (72 + v);
        }
        out[pos] = x1[ia * 2] * q[ib * 2] + x1[ia * 2 + 1] * q[ib * 2 + 1];
    } else {
        // ---- warp 2: copies (u<24) + dot4 (u>=24)
        const int u = t - 64;
        if (u < 24) {
            const int v = (u - 8) & 7;      // local idx for v2/v7
            const bool ident = u < 8;       // v1 = x1 flat
            const int idx = ident ? u : ((v & 3) * 2 + (v >> 2));
            const int pos = ident ? (32 + u) : ((u < 16) ? (40 + v) : (88 + v));
            out[pos] = x1[idx];
        } else {
            const int v = u - 24;           // 0..3 -> v3, 4..7 -> v5
            const int w = v & 3;
            const int i = w >> 1, j = w & 1;
            const bool is_v3 = v < 4;
            const float* p = is_v3 ? x1 : x2;   // v3: a.T@a, v5: b.T@a
            const int pos = is_v3 ? (48 + w) : (68 + w);
            out[pos] = p[0 + i] * x1[0 + j] + p[2 + i] * x1[2 + j]
                     + p[4 + i] * x1[4 + j] + p[6 + i] * x1[6 + j];
        }
    }
}

extern "C" void kernel_launch(void* const* d_in, const int* in_sizes, int n_in,
                              void* d_out, int out_size) {
    const float* x1 = (const float*)d_in[0];
    const float* x2 = (const float*)d_in[1];
    float* out = (float*)d_out;
    model_kernel<<<1, 96>>>(x1, x2, out);
}